// round 6
// baseline (speedup 1.0000x reference)
#include <cuda_runtime.h>
#include <math.h>

#define Bz 64
#define Tz 512
#define Hz 1024
#define H2z 2048
#define NCTA 128
#define NSLC 16            // K slices per GEMM
#define KS 64              // K per slice

// Scratch (__device__ globals; no allocation allowed)
__device__ float g_xw[(size_t)32768 * 1024];   // [B*T, H]
__device__ float g_h[Bz * Hz];
__device__ float g_hrnn[Bz * Hz];
__device__ float g_p1[NSLC * Bz * Hz];
__device__ float g_p2[NSLC * Bz * H2z];
__device__ float g_lpp[Bz][2];
__device__ unsigned g_flags[NCTA];
__device__ unsigned g_epoch;

typedef unsigned long long ull;
__device__ __forceinline__ ull dup2(float a) {
    ull r; asm("mov.b64 %0,{%1,%1};" : "=l"(r) : "f"(a)); return r;
}
__device__ __forceinline__ void fma2(ull& acc, ull a, ull w) {
    asm("fma.rn.f32x2 %0,%1,%2,%0;" : "+l"(acc) : "l"(a), "l"(w));
}

struct Smem {
    float As[32][66];     // [k][row]
    float Ws[32][130];    // [k][col]
};

// Flag-array grid barrier, persistent epoch (replay-safe, flags never reset)
__device__ __forceinline__ void grid_sync(unsigned& gen) {
    __syncthreads();
    gen++;
    if (threadIdx.x == 0)
        asm volatile("st.release.gpu.u32 [%0], %1;"
                     :: "l"(&g_flags[blockIdx.x]), "r"(gen) : "memory");
    if (threadIdx.x < NCTA) {
        unsigned v;
        do {
            asm volatile("ld.acquire.gpu.u32 %0, [%1];"
                         : "=r"(v) : "l"(&g_flags[threadIdx.x]) : "memory");
        } while ((int)(v - gen) < 0);
    }
    __syncthreads();
}

// 64x128 output tile (R3 core, unchanged except float4 A staging).
// Thread (tx=tid&15, ty=tid>>4): rows 4ty..4ty+3, cols {32m + 2tx + p}.
template<bool CG>
__device__ __forceinline__ void gemm_tile(Smem& s,
    const float* __restrict__ A, const float* __restrict__ W,
    int kb, int kcnt, ull acc[4][4])
{
    const int tid = threadIdx.x;
    const int tx = tid & 15;
    const int ty4 = (tid >> 4) << 2;
    const int ar = tid >> 3;            // A staging: row 0..31 (x2 halves)
    const int ac = (tid & 7) << 2;      // A staging: k-offset 0..28
    for (int k0 = 0; k0 < kcnt; k0 += 32) {
        // stage A: 64 rows x 32 k — 2 float4 per thread
        #pragma unroll
        for (int h = 0; h < 2; h++) {
            int row = ar + h * 32;
            const float* src = &A[row * 1024 + kb + k0 + ac];
            float4 v = CG ? __ldcg((const float4*)src)
                          : __ldg ((const float4*)src);
            s.As[ac + 0][row] = v.x;
            s.As[ac + 1][row] = v.y;
            s.As[ac + 2][row] = v.z;
            s.As[ac + 3][row] = v.w;
        }
        // stage W: 128 cols x 32 k (16 per thread, coalesced)
        #pragma unroll
        for (int i = 0; i < 16; i++) {
            int e = tid + i * 256;
            int n = e >> 5, kk = e & 31;
            s.Ws[kk][n] = __ldg(&W[n * 1024 + kb + k0 + kk]);
        }
        __syncthreads();
        #pragma unroll 8
        for (int k = 0; k < 32; k++) {
            float2 a01 = *(const float2*)&s.As[k][ty4];
            float2 a23 = *(const float2*)&s.As[k][ty4 + 2];
            ull ad0 = dup2(a01.x), ad1 = dup2(a01.y);
            ull ad2 = dup2(a23.x), ad3 = dup2(a23.y);
            ull w_[4];
            #pragma unroll
            for (int m = 0; m < 4; m++)
                w_[m] = *(const ull*)&s.Ws[k][m * 32 + tx * 2];
            #pragma unroll
            for (int m = 0; m < 4; m++) {
                fma2(acc[0][m], ad0, w_[m]);
                fma2(acc[1][m], ad1, w_[m]);
                fma2(acc[2][m], ad2, w_[m]);
                fma2(acc[3][m], ad3, w_[m]);
            }
        }
        __syncthreads();
    }
}

__device__ __forceinline__ void store_tile(float* __restrict__ Cp, int ldC,
                                           int n0, ull acc[4][4])
{
    const int tid = threadIdx.x;
    const int tx = tid & 15;
    const int ty4 = (tid >> 4) << 2;
    #pragma unroll
    for (int i = 0; i < 4; i++) {
        int b = ty4 + i;
        #pragma unroll
        for (int m = 0; m < 4; m++)
            *(float2*)&Cp[(size_t)b * ldC + n0 + m * 32 + tx * 2] =
                *(float2*)&acc[i][m];
    }
}

// ---------------------------------------------------------------------------
// Precompute: g_xw = x @ w_ih^T + b_ih + b_hh.  grid (8 n-tiles, 512 m-tiles)
// ---------------------------------------------------------------------------
__global__ __launch_bounds__(256) void xw_kernel(
    const float* __restrict__ x, const float* __restrict__ w_ih,
    const float* __restrict__ b_ih, const float* __restrict__ b_hh)
{
    __shared__ Smem s;
    const int n0 = blockIdx.x * 128;
    const int m0 = blockIdx.y * 64;
    const int tid = threadIdx.x;
    const int tx = tid & 15;
    const int ty4 = (tid >> 4) << 2;
    ull acc[4][4] = {};
    gemm_tile<false>(s, x + (size_t)m0 * 1024, w_ih + (size_t)n0 * 1024,
                     0, 1024, acc);
    #pragma unroll
    for (int i = 0; i < 4; i++) {
        size_t m = m0 + ty4 + i;
        #pragma unroll
        for (int m4 = 0; m4 < 4; m4++) {
            int n = n0 + m4 * 32 + tx * 2;
            float2 v = *(float2*)&acc[i][m4];
            v.x += __ldg(&b_ih[n])     + __ldg(&b_hh[n]);
            v.y += __ldg(&b_ih[n + 1]) + __ldg(&b_hh[n + 1]);
            *(float2*)&g_xw[m * Hz + n] = v;
        }
    }
}

// ---------------------------------------------------------------------------
// Persistent recurrent kernel: 512 steps, 128 CTAs x 256 threads.
// ---------------------------------------------------------------------------
__global__ __launch_bounds__(256, 1) void rnn_persistent(
    const float* __restrict__ eps, const float* __restrict__ w_hh,
    const float* __restrict__ w_g, const float* __restrict__ b_g,
    float* __restrict__ o_seq, float* __restrict__ o_prob,
    float* __restrict__ o_mu, float* __restrict__ o_std)
{
    __shared__ Smem s;
    const int cta = blockIdx.x;
    const int tid = threadIdx.x;
    const float LPC = -0.5f * 1.8378770664093453f * (float)Hz;

    unsigned gen = *(volatile unsigned*)&g_epoch;

    // zero recurrent state
    g_h[cta * 512 + tid]       = 0.0f;
    g_h[cta * 512 + tid + 256] = 0.0f;
    grid_sync(gen);

    for (int t = 0; t < Tz; t++) {
        // ---- P0: o_prob(t-1) + GEMM1 partial: g_p1 = h @ w_hh^T -----------
        if (t > 0 && cta < Bz && tid == 0)
            o_prob[cta * Tz + (t - 1)] =
                __ldcg(&g_lpp[cta][0]) + __ldcg(&g_lpp[cta][1]) + LPC;
        {
            const int n0 = (cta & 7) * 128;
            const int sl = cta >> 3;                 // 0..15
            ull acc[4][4] = {};
            gemm_tile<true>(s, g_h, w_hh + (size_t)n0 * 1024,
                            sl * KS, KS, acc);
            store_tile(g_p1 + (size_t)sl * (Bz * Hz), Hz, n0, acc);
        }
        grid_sync(gen);

        // ---- P1: combine + tanh -> g_hrnn ----------------------------------
        {
            #pragma unroll
            for (int u = 0; u < 2; u++) {
                int idx = cta * 512 + tid + u * 256;   // b*1024 + j
                int b = idx >> 10, j = idx & 1023;
                float v = __ldg(&g_xw[((size_t)b * Tz + t) * Hz + j]);
                float p[NSLC];
                #pragma unroll
                for (int sl = 0; sl < NSLC; sl++)
                    p[sl] = __ldcg(&g_p1[(size_t)sl * (Bz * Hz) + idx]);
                #pragma unroll
                for (int sl = 0; sl < NSLC; sl++) v += p[sl];
                g_hrnn[idx] = tanhf(v);
            }
        }
        grid_sync(gen);

        // ---- P2: GEMM2 partial: g_p2 = h_rnn @ w_g^T (2 works/CTA) ---------
        {
            #pragma unroll
            for (int w = 0; w < 2; w++) {
                int work = cta + w * 128;             // 0..255
                int n0 = (work & 15) * 128;
                int sl = work >> 4;                   // 0..15
                ull acc[4][4] = {};
                gemm_tile<true>(s, g_hrnn, w_g + (size_t)n0 * 1024,
                                sl * KS, KS, acc);
                store_tile(g_p2 + (size_t)sl * (Bz * H2z), H2z, n0, acc);
            }
        }
        grid_sync(gen);

        // ---- P3: epilogue, half batch-row per CTA ---------------------------
        {
            const int b = cta >> 1;
            const int jb = (cta & 1) * 512;
            float lp = 0.0f;
            #pragma unroll
            for (int u = 0; u < 2; u++) {
                int j = jb + tid + u * 256;
                float ss = __ldg(&b_g[j]);
                float sm = __ldg(&b_g[Hz + j]);
                #pragma unroll
                for (int sl = 0; sl < NSLC; sl++) {
                    const float* p = g_p2 + (size_t)sl * (Bz * H2z)
                                   + (size_t)b * H2z;
                    ss += __ldcg(&p[j]);
                    sm += __ldcg(&p[Hz + j]);
                }
                float sd = (ss > 20.0f) ? ss : log1pf(expf(ss));
                float e = __ldg(&eps[((size_t)b * Tz + t) * Hz + j]);
                float sample = sm + sd * e;
                size_t o = ((size_t)b * Tz + t) * Hz + j;
                o_seq[o] = sample;
                o_mu[o]  = sm;
                o_std[o] = sd;
                g_h[b * Hz + j] = sample;
                lp += -0.5f * e * e - logf(sd);
            }
            #pragma unroll
            for (int off = 16; off > 0; off >>= 1)
                lp += __shfl_xor_sync(0xffffffffu, lp, off);
            __shared__ float red[8];
            if ((tid & 31) == 0) red[tid >> 5] = lp;
            __syncthreads();
            if (tid == 0) {
                float sum = 0.0f;
                #pragma unroll
                for (int w = 0; w < 8; w++) sum += red[w];
                g_lpp[b][cta & 1] = sum;
            }
        }
        grid_sync(gen);
    }

    // final o_prob for t = 511
    if (cta < Bz && tid == 0)
        o_prob[cta * Tz + (Tz - 1)] =
            __ldcg(&g_lpp[cta][0]) + __ldcg(&g_lpp[cta][1]) + LPC;

    // persist epoch for next graph replay (flags never reset)
    if (cta == 0 && tid == 0) *(volatile unsigned*)&g_epoch = gen;
}

// ---------------------------------------------------------------------------
extern "C" void kernel_launch(void* const* d_in, const int* in_sizes, int n_in,
                              void* d_out, int out_size)
{
    const float* x    = (const float*)d_in[0];
    const float* eps  = (const float*)d_in[1];
    const float* w_ih = (const float*)d_in[2];
    const float* w_hh = (const float*)d_in[3];
    const float* b_ih = (const float*)d_in[4];
    const float* b_hh = (const float*)d_in[5];
    const float* w_g  = (const float*)d_in[6];
    const float* b_g  = (const float*)d_in[7];

    float* out = (float*)d_out;
    float* o_seq  = out;
    float* o_prob = out + (size_t)Bz * Tz * Hz;
    float* o_mu   = o_prob + (size_t)Bz * Tz;
    float* o_std  = o_mu + (size_t)Bz * Tz * Hz;

    xw_kernel<<<dim3(8, 512), 256>>>(x, w_ih, b_ih, b_hh);
    rnn_persistent<<<NCTA, 256>>>(eps, w_hh, w_g, b_g,
                                  o_seq, o_prob, o_mu, o_std);
}

// round 7
// speedup vs baseline: 1.6994x; 1.6994x over previous
#include <cuda_runtime.h>
#include <math.h>

#define Bz 64
#define Tz 512
#define Hz 1024
#define H2z 2048
#define NCTA 128
#define NS1 16             // GEMM1 k-slices (K=64)
#define NS2 8              // GEMM2 k-slices (K=128)

// Scratch (__device__ globals; no allocation allowed)
__device__ float g_xw[(size_t)32768 * 1024];   // [B*T, H]
__device__ float g_h[Bz * Hz];
__device__ float g_hrnn[Bz * Hz];
__device__ float g_p1[NS1 * Bz * Hz];
__device__ float g_p2[NS2 * Bz * H2z];
__device__ float g_lpp[Bz][2];
__device__ unsigned g_count, g_gen;

typedef unsigned long long ull;
__device__ __forceinline__ ull dup2(float a) {
    ull r; asm("mov.b64 %0,{%1,%1};" : "=l"(r) : "f"(a)); return r;
}
__device__ __forceinline__ void fma2(ull& acc, ull a, ull w) {
    asm("fma.rn.f32x2 %0,%1,%2,%0;" : "+l"(acc) : "l"(a), "l"(w));
}

struct Smem {
    float As[32][66];     // [k][row]
    float Ws[32][130];    // [k][col]
};

// Atomic-counter grid barrier (R3 original — proven fastest).
__device__ __forceinline__ void grid_sync() {
    __syncthreads();
    if (threadIdx.x == 0) {
        unsigned g = *(volatile unsigned*)&g_gen;
        __threadfence();
        unsigned old = atomicAdd(&g_count, 1u);
        if (old == NCTA - 1) {
            g_count = 0u;
            __threadfence();
            atomicAdd(&g_gen, 1u);
        } else {
            while (*(volatile unsigned*)&g_gen == g) { }
        }
        __threadfence();
    }
    __syncthreads();
}

// 64x128 output tile (R3 core, verbatim).
// Thread (tx=tid&15, ty=tid>>4): rows 4ty..4ty+3, cols {32m + 2tx + p}.
template<bool CG>
__device__ __forceinline__ void gemm_tile(Smem& s,
    const float* __restrict__ A, const float* __restrict__ W,
    int kb, int kcnt, ull acc[4][4])
{
    const int tid = threadIdx.x;
    const int tx = tid & 15;
    const int ty4 = (tid >> 4) << 2;
    for (int k0 = 0; k0 < kcnt; k0 += 32) {
        #pragma unroll
        for (int i = 0; i < 8; i++) {               // A: 64 rows x 32 k
            int e = tid + i * 256;
            int row = e >> 5, kk = e & 31;
            float v = CG ? __ldcg(&A[row * 1024 + kb + k0 + kk])
                         : __ldg (&A[row * 1024 + kb + k0 + kk]);
            s.As[kk][row] = v;
        }
        #pragma unroll
        for (int i = 0; i < 16; i++) {              // W: 128 cols x 32 k
            int e = tid + i * 256;
            int n = e >> 5, kk = e & 31;
            s.Ws[kk][n] = __ldg(&W[n * 1024 + kb + k0 + kk]);
        }
        __syncthreads();
        #pragma unroll 8
        for (int k = 0; k < 32; k++) {
            float2 a01 = *(const float2*)&s.As[k][ty4];
            float2 a23 = *(const float2*)&s.As[k][ty4 + 2];
            ull ad0 = dup2(a01.x), ad1 = dup2(a01.y);
            ull ad2 = dup2(a23.x), ad3 = dup2(a23.y);
            ull w_[4];
            #pragma unroll
            for (int m = 0; m < 4; m++)
                w_[m] = *(const ull*)&s.Ws[k][m * 32 + tx * 2];
            #pragma unroll
            for (int m = 0; m < 4; m++) {
                fma2(acc[0][m], ad0, w_[m]);
                fma2(acc[1][m], ad1, w_[m]);
                fma2(acc[2][m], ad2, w_[m]);
                fma2(acc[3][m], ad3, w_[m]);
            }
        }
        __syncthreads();
    }
}

__device__ __forceinline__ void store_tile(float* __restrict__ Cp, int ldC,
                                           int n0, ull acc[4][4])
{
    const int tid = threadIdx.x;
    const int tx = tid & 15;
    const int ty4 = (tid >> 4) << 2;
    #pragma unroll
    for (int i = 0; i < 4; i++) {
        int b = ty4 + i;
        #pragma unroll
        for (int m = 0; m < 4; m++)
            *(float2*)&Cp[(size_t)b * ldC + n0 + m * 32 + tx * 2] =
                *(float2*)&acc[i][m];
    }
}

// ---------------------------------------------------------------------------
// Precompute: g_xw = x @ w_ih^T + b_ih + b_hh.  grid (8 n-tiles, 512 m-tiles)
// ---------------------------------------------------------------------------
__global__ __launch_bounds__(256) void xw_kernel(
    const float* __restrict__ x, const float* __restrict__ w_ih,
    const float* __restrict__ b_ih, const float* __restrict__ b_hh)
{
    __shared__ Smem s;
    const int n0 = blockIdx.x * 128;
    const int m0 = blockIdx.y * 64;
    const int tid = threadIdx.x;
    const int tx = tid & 15;
    const int ty4 = (tid >> 4) << 2;
    ull acc[4][4] = {};
    gemm_tile<false>(s, x + (size_t)m0 * 1024, w_ih + (size_t)n0 * 1024,
                     0, 1024, acc);
    #pragma unroll
    for (int i = 0; i < 4; i++) {
        size_t m = m0 + ty4 + i;
        #pragma unroll
        for (int m4 = 0; m4 < 4; m4++) {
            int n = n0 + m4 * 32 + tx * 2;
            float2 v = *(float2*)&acc[i][m4];
            v.x += __ldg(&b_ih[n])     + __ldg(&b_hh[n]);
            v.y += __ldg(&b_ih[n + 1]) + __ldg(&b_hh[n + 1]);
            *(float2*)&g_xw[m * Hz + n] = v;
        }
    }
}

// ---------------------------------------------------------------------------
// Persistent recurrent kernel: 512 steps, 128 CTAs x 256 threads.
// GEMM1: 8 n-tiles(128) x 16 k-slices(64).  GEMM2: 16 n-tiles(128) x 8 k-slices(128).
// ---------------------------------------------------------------------------
__global__ __launch_bounds__(256, 1) void rnn_persistent(
    const float* __restrict__ eps, const float* __restrict__ w_hh,
    const float* __restrict__ w_g, const float* __restrict__ b_g,
    float* __restrict__ o_seq, float* __restrict__ o_prob,
    float* __restrict__ o_mu, float* __restrict__ o_std)
{
    __shared__ Smem s;
    const int cta = blockIdx.x;
    const int tid = threadIdx.x;
    const float LPC = -0.5f * 1.8378770664093453f * (float)Hz;

    // zero recurrent state
    g_h[cta * 512 + tid]       = 0.0f;
    g_h[cta * 512 + tid + 256] = 0.0f;
    grid_sync();

    for (int t = 0; t < Tz; t++) {
        // ---- P0: o_prob(t-1) + GEMM1 partial: g_p1 = h @ w_hh^T -----------
        if (t > 0 && cta < Bz && tid == 0)
            o_prob[cta * Tz + (t - 1)] =
                __ldcg(&g_lpp[cta][0]) + __ldcg(&g_lpp[cta][1]) + LPC;
        {
            const int n0 = (cta & 7) * 128;
            const int sl = cta >> 3;                 // 0..15, K=64
            ull acc[4][4] = {};
            gemm_tile<true>(s, g_h, w_hh + (size_t)n0 * 1024,
                            sl * 64, 64, acc);
            store_tile(g_p1 + (size_t)sl * (Bz * Hz), Hz, n0, acc);
        }
        grid_sync();

        // ---- P1: combine 16 partials + xw + tanh -> g_hrnn (float2) -------
        {
            int base = cta * 512 + tid * 2;          // b*1024 + j (even)
            int b = base >> 10, j = base & 1023;
            float2 v = __ldg((const float2*)&g_xw[((size_t)b * Tz + t) * Hz + j]);
            float2 acc2 = make_float2(0.f, 0.f);
            #pragma unroll
            for (int sl = 0; sl < NS1; sl += 2) {
                float2 p0 = __ldcg((const float2*)&g_p1[(size_t)sl * (Bz * Hz) + base]);
                float2 p1 = __ldcg((const float2*)&g_p1[(size_t)(sl + 1) * (Bz * Hz) + base]);
                v.x += p0.x;    v.y += p0.y;
                acc2.x += p1.x; acc2.y += p1.y;
            }
            v.x += acc2.x; v.y += acc2.y;
            *(float2*)&g_hrnn[base] = make_float2(tanhf(v.x), tanhf(v.y));
        }
        grid_sync();

        // ---- P2: GEMM2 partial: g_p2 = h_rnn @ w_g^T (1 work/CTA) ---------
        {
            const int n0 = (cta & 15) * 128;
            const int sl = cta >> 4;                 // 0..7, K=128
            ull acc[4][4] = {};
            gemm_tile<true>(s, g_hrnn, w_g + (size_t)n0 * 1024,
                            sl * 128, 128, acc);
            store_tile(g_p2 + (size_t)sl * (Bz * H2z), H2z, n0, acc);
        }
        grid_sync();

        // ---- P3: epilogue, half batch-row per CTA (float2, 2 j/thread) ----
        {
            const int b = cta >> 1;
            const int j = (cta & 1) * 512 + tid * 2;
            float2 ss = __ldg((const float2*)&b_g[j]);
            float2 mu = __ldg((const float2*)&b_g[Hz + j]);
            #pragma unroll
            for (int sl = 0; sl < NS2; sl++) {
                const float* p = g_p2 + (size_t)sl * (Bz * H2z) + (size_t)b * H2z;
                float2 a = __ldcg((const float2*)&p[j]);
                float2 c = __ldcg((const float2*)&p[Hz + j]);
                ss.x += a.x; ss.y += a.y;
                mu.x += c.x; mu.y += c.y;
            }
            float sdx = (ss.x > 20.f) ? ss.x : log1pf(__expf(ss.x));
            float sdy = (ss.y > 20.f) ? ss.y : log1pf(__expf(ss.y));
            float2 e = __ldg((const float2*)&eps[((size_t)b * Tz + t) * Hz + j]);
            float2 smp = make_float2(mu.x + sdx * e.x, mu.y + sdy * e.y);
            size_t o = ((size_t)b * Tz + t) * Hz + j;
            *(float2*)&o_seq[o] = smp;
            *(float2*)&o_mu[o]  = mu;
            *(float2*)&o_std[o] = make_float2(sdx, sdy);
            *(float2*)&g_h[b * Hz + j] = smp;

            float lp = -0.5f * (e.x * e.x + e.y * e.y)
                     - __logf(sdx) - __logf(sdy);
            #pragma unroll
            for (int off = 16; off > 0; off >>= 1)
                lp += __shfl_xor_sync(0xffffffffu, lp, off);
            __shared__ float red[8];
            if ((tid & 31) == 0) red[tid >> 5] = lp;
            __syncthreads();
            if (tid == 0) {
                float sum = 0.0f;
                #pragma unroll
                for (int w = 0; w < 8; w++) sum += red[w];
                g_lpp[b][cta & 1] = sum;
            }
        }
        grid_sync();
    }

    // final o_prob for t = 511
    if (cta < Bz && tid == 0)
        o_prob[cta * Tz + (Tz - 1)] =
            __ldcg(&g_lpp[cta][0]) + __ldcg(&g_lpp[cta][1]) + LPC;
}

// ---------------------------------------------------------------------------
extern "C" void kernel_launch(void* const* d_in, const int* in_sizes, int n_in,
                              void* d_out, int out_size)
{
    const float* x    = (const float*)d_in[0];
    const float* eps  = (const float*)d_in[1];
    const float* w_ih = (const float*)d_in[2];
    const float* w_hh = (const float*)d_in[3];
    const float* b_ih = (const float*)d_in[4];
    const float* b_hh = (const float*)d_in[5];
    const float* w_g  = (const float*)d_in[6];
    const float* b_g  = (const float*)d_in[7];

    float* out = (float*)d_out;
    float* o_seq  = out;
    float* o_prob = out + (size_t)Bz * Tz * Hz;
    float* o_mu   = o_prob + (size_t)Bz * Tz;
    float* o_std  = o_mu + (size_t)Bz * Tz * Hz;

    xw_kernel<<<dim3(8, 512), 256>>>(x, w_ih, b_ih, b_hh);
    rnn_persistent<<<NCTA, 256>>>(eps, w_hh, w_g, b_g,
                                  o_seq, o_prob, o_mu, o_std);
}

// round 8
// speedup vs baseline: 1.8437x; 1.0849x over previous
#include <cuda_runtime.h>
#include <math.h>

#define Bz 64
#define Tz 512
#define Hz 1024
#define H2z 2048
#define NCTA 128
#define NS1 16             // GEMM1 k-slices (K=64)
#define NS2 8              // GEMM2 k-slices (K=128)

// Scratch (__device__ globals; no allocation allowed)
__device__ float g_xw[(size_t)32768 * 1024];   // [B*T, H]
__device__ float g_h[Bz * Hz];
__device__ float g_hrnn[Bz * Hz];
__device__ float g_p1[NS1 * Bz * Hz];
__device__ float g_p2[NS2 * Bz * H2z];
__device__ float g_lpp[Bz][2];
__device__ unsigned g_count, g_gen;

typedef unsigned long long ull;
__device__ __forceinline__ ull dup2(float a) {
    ull r; asm("mov.b64 %0,{%1,%1};" : "=l"(r) : "f"(a)); return r;
}
__device__ __forceinline__ void fma2(ull& acc, ull a, ull w) {
    asm("fma.rn.f32x2 %0,%1,%2,%0;" : "+l"(acc) : "l"(a), "l"(w));
}

// Atomic-counter grid barrier (R3/R7 — proven).
__device__ __forceinline__ void grid_sync() {
    __syncthreads();
    if (threadIdx.x == 0) {
        unsigned g = *(volatile unsigned*)&g_gen;
        __threadfence();
        unsigned old = atomicAdd(&g_count, 1u);
        if (old == NCTA - 1) {
            g_count = 0u;
            __threadfence();
            atomicAdd(&g_gen, 1u);
        } else {
            while (*(volatile unsigned*)&g_gen == g) { }
        }
        __threadfence();
    }
    __syncthreads();
}

// Persistent-kernel SMEM: resident weight slices + per-phase A staging
struct SmemR {
    float As[128][66];     // staged A, [k][row]
    float Ws1[64][130];    // w_hh slice, [k][n] (n < 128)
    float Ws2[128][130];   // w_g  slice, [k][n]
    float red[8];
};

// xw kernel keeps its own small staging struct (R7 verbatim)
struct SmemX {
    float As[32][66];
    float Ws[32][130];
};

// Stage A[64][kcnt] (from row-major [64][1024] global, k-window kb) into As.
__device__ __forceinline__ void stage_A(float (*As)[66],
    const float* __restrict__ A, int kb, int kcnt)
{
    const int tid = threadIdx.x;
    const int row = tid >> 2;
    const int cb = (tid & 3) * (kcnt >> 2);
    for (int c = 0; c < (kcnt >> 2); c += 4) {
        float4 v = __ldcg((const float4*)&A[row * 1024 + kb + cb + c]);
        As[cb + c + 0][row] = v.x;
        As[cb + c + 1][row] = v.y;
        As[cb + c + 2][row] = v.z;
        As[cb + c + 3][row] = v.w;
    }
}

// Inner GEMM on resident SMEM operands (R7 inner loop, no chunking/syncs).
__device__ __forceinline__ void gemm_resident(
    const float (*As)[66], const float (*Ws)[130], int kcnt, ull acc[4][4])
{
    const int tid = threadIdx.x;
    const int tx = tid & 15;
    const int ty4 = (tid >> 4) << 2;
    #pragma unroll 8
    for (int k = 0; k < kcnt; k++) {
        float2 a01 = *(const float2*)&As[k][ty4];
        float2 a23 = *(const float2*)&As[k][ty4 + 2];
        ull ad0 = dup2(a01.x), ad1 = dup2(a01.y);
        ull ad2 = dup2(a23.x), ad3 = dup2(a23.y);
        ull w_[4];
        #pragma unroll
        for (int m = 0; m < 4; m++)
            w_[m] = *(const ull*)&Ws[k][m * 32 + tx * 2];
        #pragma unroll
        for (int m = 0; m < 4; m++) {
            fma2(acc[0][m], ad0, w_[m]);
            fma2(acc[1][m], ad1, w_[m]);
            fma2(acc[2][m], ad2, w_[m]);
            fma2(acc[3][m], ad3, w_[m]);
        }
    }
}

__device__ __forceinline__ void store_tile(float* __restrict__ Cp, int ldC,
                                           int n0, ull acc[4][4])
{
    const int tid = threadIdx.x;
    const int tx = tid & 15;
    const int ty4 = (tid >> 4) << 2;
    #pragma unroll
    for (int i = 0; i < 4; i++) {
        int b = ty4 + i;
        #pragma unroll
        for (int m = 0; m < 4; m++)
            *(float2*)&Cp[(size_t)b * ldC + n0 + m * 32 + tx * 2] =
                *(float2*)&acc[i][m];
    }
}

// ---------------------------------------------------------------------------
// Precompute: g_xw = x @ w_ih^T + b_ih + b_hh (R7 verbatim)
// ---------------------------------------------------------------------------
__global__ __launch_bounds__(256) void xw_kernel(
    const float* __restrict__ x, const float* __restrict__ w_ih,
    const float* __restrict__ b_ih, const float* __restrict__ b_hh)
{
    __shared__ SmemX s;
    const int n0 = blockIdx.x * 128;
    const int m0 = blockIdx.y * 64;
    const int tid = threadIdx.x;
    const int tx = tid & 15;
    const int ty4 = (tid >> 4) << 2;
    ull acc[4][4] = {};

    const float* A = x + (size_t)m0 * 1024;
    const float* W = w_ih + (size_t)n0 * 1024;
    for (int k0 = 0; k0 < 1024; k0 += 32) {
        #pragma unroll
        for (int i = 0; i < 8; i++) {
            int e = tid + i * 256;
            int row = e >> 5, kk = e & 31;
            s.As[kk][row] = __ldg(&A[row * 1024 + k0 + kk]);
        }
        #pragma unroll
        for (int i = 0; i < 16; i++) {
            int e = tid + i * 256;
            int n = e >> 5, kk = e & 31;
            s.Ws[kk][n] = __ldg(&W[n * 1024 + k0 + kk]);
        }
        __syncthreads();
        #pragma unroll 8
        for (int k = 0; k < 32; k++) {
            float2 a01 = *(const float2*)&s.As[k][ty4];
            float2 a23 = *(const float2*)&s.As[k][ty4 + 2];
            ull ad0 = dup2(a01.x), ad1 = dup2(a01.y);
            ull ad2 = dup2(a23.x), ad3 = dup2(a23.y);
            ull w_[4];
            #pragma unroll
            for (int m = 0; m < 4; m++)
                w_[m] = *(const ull*)&s.Ws[k][m * 32 + tx * 2];
            #pragma unroll
            for (int m = 0; m < 4; m++) {
                fma2(acc[0][m], ad0, w_[m]);
                fma2(acc[1][m], ad1, w_[m]);
                fma2(acc[2][m], ad2, w_[m]);
                fma2(acc[3][m], ad3, w_[m]);
            }
        }
        __syncthreads();
    }
    #pragma unroll
    for (int i = 0; i < 4; i++) {
        size_t m = m0 + ty4 + i;
        #pragma unroll
        for (int m4 = 0; m4 < 4; m4++) {
            int n = n0 + m4 * 32 + tx * 2;
            float2 v = *(float2*)&acc[i][m4];
            v.x += __ldg(&b_ih[n])     + __ldg(&b_hh[n]);
            v.y += __ldg(&b_ih[n + 1]) + __ldg(&b_hh[n + 1]);
            *(float2*)&g_xw[m * Hz + n] = v;
        }
    }
}

// ---------------------------------------------------------------------------
// Persistent recurrent kernel: 512 steps, 128 CTAs x 256 threads.
// Weights SMEM-resident. GEMM1: 8n x 16sl(K=64). GEMM2: 16n x 8sl(K=128).
// ---------------------------------------------------------------------------
__global__ __launch_bounds__(256, 1) void rnn_persistent(
    const float* __restrict__ eps, const float* __restrict__ w_hh,
    const float* __restrict__ w_g, const float* __restrict__ b_g,
    float* __restrict__ o_seq, float* __restrict__ o_prob,
    float* __restrict__ o_mu, float* __restrict__ o_std)
{
    extern __shared__ unsigned char smraw[];
    SmemR& sm = *(SmemR*)smraw;
    const int cta = blockIdx.x;
    const int tid = threadIdx.x;
    const float LPC = -0.5f * 1.8378770664093453f * (float)Hz;

    const int n01 = (cta & 7)  * 128, kb1 = (cta >> 3) * 64;   // GEMM1 tile
    const int n02 = (cta & 15) * 128, kb2 = (cta >> 4) * 128;  // GEMM2 tile
    const size_t p1off = (size_t)(cta >> 3) * (Bz * Hz);
    const size_t p2off = (size_t)(cta >> 4) * (Bz * H2z);

    // zero recurrent state
    g_h[cta * 512 + tid]       = 0.0f;
    g_h[cta * 512 + tid + 256] = 0.0f;

    // preload resident weight slices (coalesced along k; once per launch)
    for (int e = tid; e < 128 * 64; e += 256) {
        int k = e & 63, n = e >> 6;
        sm.Ws1[k][n] = __ldg(&w_hh[(size_t)(n01 + n) * 1024 + kb1 + k]);
    }
    for (int e = tid; e < 128 * 128; e += 256) {
        int k = e & 127, n = e >> 7;
        sm.Ws2[k][n] = __ldg(&w_g[(size_t)(n02 + n) * 1024 + kb2 + k]);
    }
    grid_sync();

    for (int t = 0; t < Tz; t++) {
        // ---- P0: o_prob(t-1) + GEMM1 partial: g_p1 = h @ w_hh^T -----------
        if (t > 0 && cta < Bz && tid == 0)
            o_prob[cta * Tz + (t - 1)] =
                __ldcg(&g_lpp[cta][0]) + __ldcg(&g_lpp[cta][1]) + LPC;
        stage_A(sm.As, g_h, kb1, 64);
        __syncthreads();
        {
            ull acc[4][4] = {};
            gemm_resident(sm.As, sm.Ws1, 64, acc);
            store_tile(g_p1 + p1off, Hz, n01, acc);
        }
        grid_sync();

        // ---- P1: combine 16 partials + xw + tanh -> g_hrnn (float2) -------
        {
            int base = cta * 512 + tid * 2;          // b*1024 + j (even)
            int b = base >> 10, j = base & 1023;
            float2 v = __ldg((const float2*)&g_xw[((size_t)b * Tz + t) * Hz + j]);
            float2 acc2 = make_float2(0.f, 0.f);
            #pragma unroll
            for (int sl = 0; sl < NS1; sl += 2) {
                float2 p0 = __ldcg((const float2*)&g_p1[(size_t)sl * (Bz * Hz) + base]);
                float2 p1 = __ldcg((const float2*)&g_p1[(size_t)(sl + 1) * (Bz * Hz) + base]);
                v.x += p0.x;    v.y += p0.y;
                acc2.x += p1.x; acc2.y += p1.y;
            }
            v.x += acc2.x; v.y += acc2.y;
            *(float2*)&g_hrnn[base] = make_float2(tanhf(v.x), tanhf(v.y));
        }
        grid_sync();

        // ---- P2: GEMM2 partial: g_p2 = h_rnn @ w_g^T ----------------------
        stage_A(sm.As, g_hrnn, kb2, 128);
        __syncthreads();
        {
            ull acc[4][4] = {};
            gemm_resident(sm.As, sm.Ws2, 128, acc);
            store_tile(g_p2 + p2off, H2z, n02, acc);
        }
        grid_sync();

        // ---- P3: epilogue, half batch-row per CTA (float2, 2 j/thread) ----
        {
            const int b = cta >> 1;
            const int j = (cta & 1) * 512 + tid * 2;
            float2 ss = __ldg((const float2*)&b_g[j]);
            float2 mu = __ldg((const float2*)&b_g[Hz + j]);
            #pragma unroll
            for (int sl = 0; sl < NS2; sl++) {
                const float* p = g_p2 + (size_t)sl * (Bz * H2z) + (size_t)b * H2z;
                float2 a = __ldcg((const float2*)&p[j]);
                float2 c = __ldcg((const float2*)&p[Hz + j]);
                ss.x += a.x; ss.y += a.y;
                mu.x += c.x; mu.y += c.y;
            }
            float sdx = (ss.x > 20.f) ? ss.x : log1pf(__expf(ss.x));
            float sdy = (ss.y > 20.f) ? ss.y : log1pf(__expf(ss.y));
            float2 e = __ldg((const float2*)&eps[((size_t)b * Tz + t) * Hz + j]);
            float2 smp = make_float2(mu.x + sdx * e.x, mu.y + sdy * e.y);
            size_t o = ((size_t)b * Tz + t) * Hz + j;
            *(float2*)&o_seq[o] = smp;
            *(float2*)&o_mu[o]  = mu;
            *(float2*)&o_std[o] = make_float2(sdx, sdy);
            *(float2*)&g_h[b * Hz + j] = smp;

            float lp = -0.5f * (e.x * e.x + e.y * e.y)
                     - __logf(sdx) - __logf(sdy);
            #pragma unroll
            for (int off = 16; off > 0; off >>= 1)
                lp += __shfl_xor_sync(0xffffffffu, lp, off);
            if ((tid & 31) == 0) sm.red[tid >> 5] = lp;
            __syncthreads();
            if (tid == 0) {
                float sum = 0.0f;
                #pragma unroll
                for (int w = 0; w < 8; w++) sum += sm.red[w];
                g_lpp[b][cta & 1] = sum;
            }
        }
        grid_sync();
    }

    // final o_prob for t = 511
    if (cta < Bz && tid == 0)
        o_prob[cta * Tz + (Tz - 1)] =
            __ldcg(&g_lpp[cta][0]) + __ldcg(&g_lpp[cta][1]) + LPC;
}

// ---------------------------------------------------------------------------
extern "C" void kernel_launch(void* const* d_in, const int* in_sizes, int n_in,
                              void* d_out, int out_size)
{
    const float* x    = (const float*)d_in[0];
    const float* eps  = (const float*)d_in[1];
    const float* w_ih = (const float*)d_in[2];
    const float* w_hh = (const float*)d_in[3];
    const float* b_ih = (const float*)d_in[4];
    const float* b_hh = (const float*)d_in[5];
    const float* w_g  = (const float*)d_in[6];
    const float* b_g  = (const float*)d_in[7];

    float* out = (float*)d_out;
    float* o_seq  = out;
    float* o_prob = out + (size_t)Bz * Tz * Hz;
    float* o_mu   = o_prob + (size_t)Bz * Tz;
    float* o_std  = o_mu + (size_t)Bz * Tz * Hz;

    cudaFuncSetAttribute(rnn_persistent,
                         cudaFuncAttributeMaxDynamicSharedMemorySize,
                         (int)sizeof(SmemR));

    xw_kernel<<<dim3(8, 512), 256>>>(x, w_ih, b_ih, b_hh);
    rnn_persistent<<<NCTA, 256, sizeof(SmemR)>>>(eps, w_hh, w_g, b_g,
                                                 o_seq, o_prob, o_mu, o_std);
}